// round 8
// baseline (speedup 1.0000x reference)
#include <cuda_runtime.h>
#include <cuda_fp16.h>
#include <cstdint>

#define B_SZ   32768
#define IN_DIM 128
#define ACT    512
#define MAXD   1024

// ---- smem byte offsets (double-buffered k=32 chunks) ----
#define PA_A(b,p)    ((b)*20480 + (p)*10240)                  // prev/inputs [128][80B], 0..40960
#define PA_W(b,p)    (40960 + (b)*10240 + (p)*5120)           // wres[32][144B] / Win[64][80B]
#define PB_INP(b,p)  ((b)*20480 + (p)*10240)
#define PB_W(b,mt,p) (40960 + (b)*15360 + ((mt)*2+(p))*2560)  // gate W [32][80B]
#define Z_OFF   71680          // fp32 [128][stride 72 floats]
#define LK_OFF  108544
#define TH_OFF  108800
#define SMEM_BYTES 109056

__device__ __forceinline__ void ldsm4(uint32_t r[4], uint32_t a) {
    asm volatile("ldmatrix.sync.aligned.m8n8.x4.shared.b16 {%0,%1,%2,%3}, [%4];"
        : "=r"(r[0]), "=r"(r[1]), "=r"(r[2]), "=r"(r[3]) : "r"(a));
}
__device__ __forceinline__ void ldsm4t(uint32_t r[4], uint32_t a) {
    asm volatile("ldmatrix.sync.aligned.m8n8.x4.trans.shared.b16 {%0,%1,%2,%3}, [%4];"
        : "=r"(r[0]), "=r"(r[1]), "=r"(r[2]), "=r"(r[3]) : "r"(a));
}
__device__ __forceinline__ uint32_t smem_u32(const void* p) {
    uint32_t a;
    asm("{ .reg .u64 t; cvta.to.shared.u64 t, %1; cvt.u32.u64 %0, t; }" : "=r"(a) : "l"(p));
    return a;
}
__device__ __forceinline__ void mma16(float c[4], const uint32_t a[4], uint32_t b0, uint32_t b1) {
    asm volatile("mma.sync.aligned.m16n8k16.row.col.f32.f16.f16.f32 "
        "{%0,%1,%2,%3},{%4,%5,%6,%7},{%8,%9},{%0,%1,%2,%3};"
        : "+f"(c[0]), "+f"(c[1]), "+f"(c[2]), "+f"(c[3])
        : "r"(a[0]), "r"(a[1]), "r"(a[2]), "r"(a[3]), "r"(b0), "r"(b1));
}
__device__ __forceinline__ uint32_t packh2(float lo, float hi) {
    uint32_t r;
    asm("cvt.rn.f16x2.f32 %0, %1, %2;" : "=r"(r) : "f"(hi), "f"(lo));
    return r;
}
__device__ __forceinline__ float2 unph2(uint32_t p) {
    __half2 h;
    *reinterpret_cast<uint32_t*>(&h) = p;
    return __half22float2(h);
}
__device__ __forceinline__ void split_pair(float x0, float x1, uint32_t& ph, uint32_t& pm) {
    ph = packh2(x0, x1);
    float2 h = unph2(ph);
    pm = packh2(x0 - h.x, x1 - h.y);
}
__device__ __forceinline__ void three(float c[4],
                                      const uint32_t ah[4], const uint32_t am[4],
                                      uint32_t bh0, uint32_t bh1, uint32_t bm0, uint32_t bm1) {
    mma16(c, ah, bh0, bh1);
    mma16(c, ah, bm0, bm1);
    mma16(c, am, bh0, bh1);
}
__device__ __forceinline__ float epi(float z, float gi_, float gf_, float go_,
                                     float p, float lk, float th) {
    float ig = 1.0f / (1.0f + expf(-gi_));
    float fg = 1.0f / (1.0f + expf(-gf_));
    float og = 1.0f / (1.0f + expf(-go_));
    float s = (1.0f - lk) * (fg * p) + lk * tanhf(ig * z);
    s *= og;
    return (s > th) ? (s - th) : s;
}

__global__ __launch_bounds__(256, 2)
void gser_pl(const float* __restrict__ inputs,
             const float* __restrict__ prev,
             const float* __restrict__ Wres,
             const float* __restrict__ Win,
             const float* __restrict__ Wgate,
             const float* __restrict__ leakp,
             const float* __restrict__ thrp,
             float* __restrict__ out)
{
    const int bx = blockIdx.x;
    const int m0 = blockIdx.y * 128;
    const int n0 = bx * 64;
    const int tid = threadIdx.x;
    const int wid = tid >> 5;
    const int lane = tid & 31;
    const int m0A = (wid & 3) * 32;       // phase A warp grid 4m x 2n (32x32 tiles)
    const int n0A = (wid >> 2) * 32;
    const int n0B = (wid >> 2) * 16;      // phase B warp grid 4m x 2n (32x16 tiles)
    const int rbase = (wid & 3) + ((wid >> 2) << 3);
    const int lq = lane & 15;
    const int rd = (lane >> 4) << 2;      // +4 row for upper half-warp (bank-safe pairing)

    extern __shared__ char smc[];
    const uint32_t sb = smem_u32(smc);
    float* s_lk = reinterpret_cast<float*>(smc + LK_OFF);
    float* s_th = reinterpret_cast<float*>(smc + TH_OFF);
    float* s_z  = reinterpret_cast<float*>(smc + Z_OFF);

    // zero-fill pad: out[m0:m0+128, 512+bx*64 : +64)
    {
        const float4 z4 = make_float4(0.f, 0.f, 0.f, 0.f);
        #pragma unroll
        for (int it = 0; it < 8; ++it) {
            int idx = tid + 256 * it;
            int r = idx >> 4, q = idx & 15;
            *reinterpret_cast<float4*>(out + (size_t)(m0 + r) * MAXD + ACT + bx * 64 + 4 * q) = z4;
        }
    }
    if (tid < 64) {
        s_lk[tid] = 1.0f / (1.0f + expf(-leakp[n0 + tid]));
        s_th[tid] = log1pf(expf(thrp[n0 + tid]));
    }

    // ldsm lane-address pieces
    const uint32_t aOff = (uint32_t)((m0A + (lane & 15)) * 80) + ((lane >> 4) << 4);
    const uint32_t bTr  = (uint32_t)(((lane & 7) + ((lane >> 3) & 1) * 8) * 144)
                        + (uint32_t)((n0A + ((lane >> 4) << 3)) * 2);
    const uint32_t bWn  = (uint32_t)((n0A + (lane & 7) + ((lane >> 4) << 3)) * 80)
                        + ((lane & 8) ? 16u : 0u);
    const uint32_t bGt  = (uint32_t)((n0B + (lane & 7) + ((lane >> 4) << 3)) * 80)
                        + ((lane & 8) ? 16u : 0u);

    float2 pa[8];
    float2 pb[4];
    float2 pw[3][2];

    // ---------------- lambdas ----------------
    auto ldgA = [&](int c) {
        if (c < 16) {
            const int kc = 32 * c;
            #pragma unroll
            for (int it = 0; it < 8; ++it) {
                int r = rbase + 16 * it + rd;
                pa[it] = *reinterpret_cast<const float2*>(prev + (size_t)(m0 + r) * MAXD + kc + 2 * lq);
            }
            #pragma unroll
            for (int it = 0; it < 4; ++it) {
                int r = wid * 4 + it;
                pb[it] = *reinterpret_cast<const float2*>(Wres + (size_t)(kc + r) * MAXD + n0 + 2 * lane);
            }
        } else {
            const int kc = 32 * (c - 16);
            #pragma unroll
            for (int it = 0; it < 8; ++it) {
                int r = rbase + 16 * it + rd;
                pa[it] = *reinterpret_cast<const float2*>(inputs + (size_t)(m0 + r) * IN_DIM + kc + 2 * lq);
            }
            #pragma unroll
            for (int it = 0; it < 4; ++it) {
                int r = rbase + 16 * it + rd;
                pb[it] = *reinterpret_cast<const float2*>(Win + (size_t)(n0 + r) * IN_DIM + kc + 2 * lq);
            }
        }
    };
    auto stsA = [&](int c, int b) {
        #pragma unroll
        for (int it = 0; it < 8; ++it) {
            int r = rbase + 16 * it + rd;
            uint32_t h, m;
            split_pair(pa[it].x, pa[it].y, h, m);
            *reinterpret_cast<uint32_t*>(smc + PA_A(b, 0) + r * 80 + 4 * lq) = h;
            *reinterpret_cast<uint32_t*>(smc + PA_A(b, 1) + r * 80 + 4 * lq) = m;
        }
        if (c < 16) {
            #pragma unroll
            for (int it = 0; it < 4; ++it) {
                int r = wid * 4 + it;
                uint32_t h, m;
                split_pair(pb[it].x, pb[it].y, h, m);
                *reinterpret_cast<uint32_t*>(smc + PA_W(b, 0) + r * 144 + 4 * lane) = h;
                *reinterpret_cast<uint32_t*>(smc + PA_W(b, 1) + r * 144 + 4 * lane) = m;
            }
        } else {
            #pragma unroll
            for (int it = 0; it < 4; ++it) {
                int r = rbase + 16 * it + rd;
                uint32_t h, m;
                split_pair(pb[it].x, pb[it].y, h, m);
                *reinterpret_cast<uint32_t*>(smc + PA_W(b, 0) + r * 80 + 4 * lq) = h;
                *reinterpret_cast<uint32_t*>(smc + PA_W(b, 1) + r * 80 + 4 * lq) = m;
            }
        }
    };

    float z[2][4][4];
    #pragma unroll
    for (int a = 0; a < 2; ++a)
        #pragma unroll
        for (int b = 0; b < 4; ++b)
            #pragma unroll
            for (int k = 0; k < 4; ++k) z[a][b][k] = 0.f;

    auto computeA = [&](int c, int b) {
        const bool tr = (c < 16);
        #pragma unroll
        for (int ks = 0; ks < 2; ++ks) {
            uint32_t aF[2][2][4];
            #pragma unroll
            for (int p = 0; p < 2; ++p) {
                ldsm4(aF[p][0], sb + PA_A(b, p) + aOff + ks * 32);
                ldsm4(aF[p][1], sb + PA_A(b, p) + aOff + 16 * 80 + ks * 32);
            }
            uint32_t bF[2][2][4];
            if (tr) {
                #pragma unroll
                for (int p = 0; p < 2; ++p)
                    #pragma unroll
                    for (int j = 0; j < 2; ++j)
                        ldsm4t(bF[p][j], sb + PA_W(b, p) + bTr + (uint32_t)(ks * 16 * 144) + j * 32);
            } else {
                #pragma unroll
                for (int p = 0; p < 2; ++p)
                    #pragma unroll
                    for (int j = 0; j < 2; ++j)
                        ldsm4(bF[p][j], sb + PA_W(b, p) + bWn + (uint32_t)(j * 16 * 80) + ks * 32);
            }
            #pragma unroll
            for (int mi = 0; mi < 2; ++mi)
                #pragma unroll
                for (int j = 0; j < 2; ++j) {
                    three(z[mi][2 * j],     aF[0][mi], aF[1][mi],
                          bF[0][j][0], bF[0][j][1], bF[1][j][0], bF[1][j][1]);
                    three(z[mi][2 * j + 1], aF[0][mi], aF[1][mi],
                          bF[0][j][2], bF[0][j][3], bF[1][j][2], bF[1][j][3]);
                }
        }
    };

    // ================= Phase A pipeline: 20 chunks of k=32 =================
    ldgA(0);
    stsA(0, 0);
    ldgA(1);
    __syncthreads();
    for (int c = 0; c < 20; ++c) {
        computeA(c, c & 1);
        if (c < 19) {
            __syncthreads();
            stsA(c + 1, (c + 1) & 1);
            if (c < 18) ldgA(c + 2);
            __syncthreads();
        }
    }

    // park z to smem [128][72 floats]
    {
        const int tq = lane >> 2, tr2 = lane & 3;
        #pragma unroll
        for (int mi = 0; mi < 2; ++mi) {
            const int r0 = m0A + mi * 16 + tq;
            #pragma unroll
            for (int j = 0; j < 4; ++j) {
                const int cc = n0A + j * 8 + 2 * tr2;
                *reinterpret_cast<float2*>(s_z + (size_t)r0 * 72 + cc)       = make_float2(z[mi][j][0], z[mi][j][1]);
                *reinterpret_cast<float2*>(s_z + (size_t)(r0 + 8) * 72 + cc) = make_float2(z[mi][j][2], z[mi][j][3]);
            }
        }
    }
    __syncthreads();   // z visible; phase-A buffers free for phase B

    // ================= Phase B pipeline: 8 chunks (2 halves x K=128/32) =====
    float g[3][2][2][4];
    #pragma unroll
    for (int a = 0; a < 3; ++a)
        #pragma unroll
        for (int b = 0; b < 2; ++b)
            #pragma unroll
            for (int j = 0; j < 2; ++j)
                #pragma unroll
                for (int k = 0; k < 4; ++k) g[a][b][j][k] = 0.f;

    auto ldgB = [&](int cb) {
        const int h = cb >> 2;
        const int kc = 32 * (cb & 3);
        #pragma unroll
        for (int it = 0; it < 8; ++it) {
            int r = rbase + 16 * it + rd;
            pa[it] = *reinterpret_cast<const float2*>(inputs + (size_t)(m0 + r) * IN_DIM + kc + 2 * lq);
        }
        #pragma unroll
        for (int mt = 0; mt < 3; ++mt)
            #pragma unroll
            for (int it = 0; it < 2; ++it) {
                int r = rbase + 16 * it + rd;
                pw[mt][it] = *reinterpret_cast<const float2*>(
                    Wgate + (size_t)(mt * ACT + n0 + 32 * h + r) * IN_DIM + kc + 2 * lq);
            }
    };
    auto stsB = [&](int b) {
        #pragma unroll
        for (int it = 0; it < 8; ++it) {
            int r = rbase + 16 * it + rd;
            uint32_t h, m;
            split_pair(pa[it].x, pa[it].y, h, m);
            *reinterpret_cast<uint32_t*>(smc + PB_INP(b, 0) + r * 80 + 4 * lq) = h;
            *reinterpret_cast<uint32_t*>(smc + PB_INP(b, 1) + r * 80 + 4 * lq) = m;
        }
        #pragma unroll
        for (int mt = 0; mt < 3; ++mt)
            #pragma unroll
            for (int it = 0; it < 2; ++it) {
                int r = rbase + 16 * it + rd;
                uint32_t h, m;
                split_pair(pw[mt][it].x, pw[mt][it].y, h, m);
                *reinterpret_cast<uint32_t*>(smc + PB_W(b, mt, 0) + r * 80 + 4 * lq) = h;
                *reinterpret_cast<uint32_t*>(smc + PB_W(b, mt, 1) + r * 80 + 4 * lq) = m;
            }
    };
    auto computeB = [&](int b) {
        #pragma unroll
        for (int ks = 0; ks < 2; ++ks) {
            uint32_t aF[2][2][4];
            #pragma unroll
            for (int p = 0; p < 2; ++p) {
                ldsm4(aF[p][0], sb + PB_INP(b, p) + aOff + ks * 32);
                ldsm4(aF[p][1], sb + PB_INP(b, p) + aOff + 16 * 80 + ks * 32);
            }
            #pragma unroll
            for (int mt = 0; mt < 3; ++mt) {
                uint32_t bF[2][4];
                #pragma unroll
                for (int p = 0; p < 2; ++p)
                    ldsm4(bF[p], sb + PB_W(b, mt, p) + bGt + ks * 32);
                #pragma unroll
                for (int mi = 0; mi < 2; ++mi) {
                    three(g[mt][mi][0], aF[0][mi], aF[1][mi], bF[0][0], bF[0][1], bF[1][0], bF[1][1]);
                    three(g[mt][mi][1], aF[0][mi], aF[1][mi], bF[0][2], bF[0][3], bF[1][2], bF[1][3]);
                }
            }
        }
    };
    auto epilogue = [&](int h) {
        const int tq = lane >> 2, tr2 = lane & 3;
        #pragma unroll
        for (int mi = 0; mi < 2; ++mi) {
            const int rr0 = m0A + mi * 16 + tq;
            const int mg0 = m0 + rr0;
            const int mg1 = mg0 + 8;
            #pragma unroll
            for (int ni = 0; ni < 2; ++ni) {
                const int cc = 32 * h + n0B + ni * 8 + 2 * tr2;
                const int ng = n0 + cc;
                const float lk0 = s_lk[cc], lk1 = s_lk[cc + 1];
                const float th0 = s_th[cc], th1 = s_th[cc + 1];
                const float2 z0 = *reinterpret_cast<const float2*>(s_z + (size_t)rr0 * 72 + cc);
                const float2 z1 = *reinterpret_cast<const float2*>(s_z + (size_t)(rr0 + 8) * 72 + cc);
                const float2 p0 = *reinterpret_cast<const float2*>(prev + (size_t)mg0 * MAXD + ng);
                const float2 p1 = *reinterpret_cast<const float2*>(prev + (size_t)mg1 * MAXD + ng);
                float2 o0, o1;
                o0.x = epi(z0.x, g[0][mi][ni][0], g[1][mi][ni][0], g[2][mi][ni][0], p0.x, lk0, th0);
                o0.y = epi(z0.y, g[0][mi][ni][1], g[1][mi][ni][1], g[2][mi][ni][1], p0.y, lk1, th1);
                o1.x = epi(z1.x, g[0][mi][ni][2], g[1][mi][ni][2], g[2][mi][ni][2], p1.x, lk0, th0);
                o1.y = epi(z1.y, g[0][mi][ni][3], g[1][mi][ni][3], g[2][mi][ni][3], p1.y, lk1, th1);
                *reinterpret_cast<float2*>(out + (size_t)mg0 * MAXD + ng) = o0;
                *reinterpret_cast<float2*>(out + (size_t)mg1 * MAXD + ng) = o1;
            }
        }
        #pragma unroll
        for (int a = 0; a < 3; ++a)
            #pragma unroll
            for (int b = 0; b < 2; ++b)
                #pragma unroll
                for (int j = 0; j < 2; ++j)
                    #pragma unroll
                    for (int k = 0; k < 4; ++k) g[a][b][j][k] = 0.f;
    };

    ldgB(0);
    stsB(0);
    ldgB(1);
    __syncthreads();
    for (int cb = 0; cb < 8; ++cb) {
        computeB(cb & 1);
        if (cb < 7) {
            __syncthreads();
            stsB((cb + 1) & 1);
            if (cb < 6) ldgB(cb + 2);
            __syncthreads();
        }
        if (cb == 3) epilogue(0);
    }
    epilogue(1);
}

extern "C" void kernel_launch(void* const* d_in, const int* in_sizes, int n_in,
                              void* d_out, int out_size)
{
    const float* inputs = (const float*)d_in[0];
    const float* prev   = (const float*)d_in[1];
    const float* Wres   = (const float*)d_in[2];
    const float* Win    = (const float*)d_in[3];
    const float* Wgate  = (const float*)d_in[4];
    const float* leakp  = (const float*)d_in[5];
    const float* thrp   = (const float*)d_in[6];
    float* out = (float*)d_out;

    cudaFuncSetAttribute(gser_pl, cudaFuncAttributeMaxDynamicSharedMemorySize, SMEM_BYTES);

    dim3 grid(8, B_SZ / 128);
    gser_pl<<<grid, 256, SMEM_BYTES>>>(inputs, prev, Wres, Win, Wgate, leakp, thrp, out);
}